// round 12
// baseline (speedup 1.0000x reference)
#include <cuda_runtime.h>
#include <math.h>
#include <stdint.h>

// Multiresolution hash-grid encoding: spatial sort + dense pair-grids.
//
// Pipeline (graph-capturable, scratch in __device__ globals):
//  K0 zero_hist : clear 32768-bucket histogram
//  K1 hist      : Morton bucket (res 32); atomicAdd rank -> (bucket, rank)
//  K2 scan      : exclusive scan -> bucket bases (single block)
//  K3 scatter   : pos = base+rank (no atomics); sorted float4(x,y,z,idx)
//  K3b build    : dense pair-grid for levels 0..13: cell (cx,cy,cz) holds
//                 float4(v(cx,..), v(cx+1,..)). Build reads are ~coalesced
//                 (consecutive cx -> h = cx ^ g spans 1-2 table lines).
//  K4 main      : one thread per sorted point. Levels 0..13 read the dense
//                 grid (spatially local -> few L1 wavefronts per warp);
//                 levels 14..15 use the hash path with x-pair float4 merge.
//                 All path splits are warp-uniform (loop over levels).

#define N_LEVELS 16
#define N_DENSE  14
#define LOG2_T   19
#define T_MASK   ((1u << LOG2_T) - 1u)
#define P1       2654435761u
#define P2       805459861u

#define SORT_RES   32
#define N_BUCKETS  (SORT_RES * SORT_RES * SORT_RES)
#define MAX_N      1100000
#define G_CAP      3000000          // float4 cells; levels 0..13 need ~2.72M

__device__ unsigned g_hist[N_BUCKETS];
__device__ unsigned g_base[N_BUCKETS];
__device__ unsigned g_bucket[MAX_N];
__device__ unsigned g_rank[MAX_N];
__device__ float4   g_xs[MAX_N];
__device__ float4   g_dense[G_CAP];

struct Params {
    float resf[N_LEVELS];
    int   off[N_DENSE];       // float4 offset per dense level
    int   cum[N_DENSE + 1];   // cumulative cells (for 1D build launch)
};

// ------------------------------------------------------------------ morton
__device__ __forceinline__ unsigned expand_bits(unsigned v) {
    v = (v * 0x00010001u) & 0xFF0000FFu;
    v = (v * 0x00000101u) & 0x0F00F00Fu;
    v = (v * 0x00000011u) & 0xC30C30C3u;
    v = (v * 0x00000005u) & 0x49249249u;
    return v;
}

__device__ __forceinline__ unsigned bucket_of(float px, float py, float pz) {
    int cx = (int)(px * (float)SORT_RES);
    int cy = (int)(py * (float)SORT_RES);
    int cz = (int)(pz * (float)SORT_RES);
    cx = min(max(cx, 0), SORT_RES - 1);
    cy = min(max(cy, 0), SORT_RES - 1);
    cz = min(max(cz, 0), SORT_RES - 1);
    return expand_bits((unsigned)cx)
         | (expand_bits((unsigned)cy) << 1)
         | (expand_bits((unsigned)cz) << 2);
}

// ---------------------------------------------------------------- sorting
__global__ void zero_hist_kernel() {
    int i = blockIdx.x * blockDim.x + threadIdx.x;
    if (i < N_BUCKETS) g_hist[i] = 0u;
}

__global__ __launch_bounds__(256) void hist_kernel(const float* __restrict__ x, int N) {
    int n = blockIdx.x * 256 + threadIdx.x;
    if (n >= N) return;
    unsigned b = bucket_of(x[n * 3 + 0], x[n * 3 + 1], x[n * 3 + 2]);
    unsigned r = atomicAdd(&g_hist[b], 1u);
    g_bucket[n] = b;
    g_rank[n]   = r;
}

__global__ __launch_bounds__(1024) void scan_kernel() {
    __shared__ unsigned partial[1024];
    const int t = threadIdx.x;
    unsigned local[32];
    unsigned s = 0;
    #pragma unroll
    for (int j = 0; j < 32; ++j) { local[j] = g_hist[t * 32 + j]; s += local[j]; }
    partial[t] = s;
    __syncthreads();
    for (int d = 1; d < 1024; d <<= 1) {
        unsigned v = (t >= d) ? partial[t - d] : 0u;
        __syncthreads();
        partial[t] += v;
        __syncthreads();
    }
    unsigned run = (t > 0) ? partial[t - 1] : 0u;
    #pragma unroll
    for (int j = 0; j < 32; ++j) { g_base[t * 32 + j] = run; run += local[j]; }
}

__global__ __launch_bounds__(256) void scatter_kernel(const float* __restrict__ x, int N) {
    int n = blockIdx.x * 256 + threadIdx.x;
    if (n >= N) return;
    const unsigned pos = g_base[g_bucket[n]] + g_rank[n];
    g_xs[pos] = make_float4(x[n * 3 + 0], x[n * 3 + 1], x[n * 3 + 2],
                            __int_as_float(n));
}

// ------------------------------------------------------------------ build
__global__ __launch_bounds__(256) void build_dense_kernel(
    const float2* __restrict__ table, Params p)
{
    const int gi = blockIdx.x * 256 + threadIdx.x;
    if (gi >= p.cum[N_DENSE]) return;

    // find level (small uniform-ish loop; consecutive threads same level)
    int l = 0;
    #pragma unroll
    for (int k = 1; k < N_DENSE; ++k) if (gi >= p.cum[k]) l = k;

    const int i = gi - p.cum[l];
    const int r = (int)p.resf[l];
    const int W = r, H = r + 1;

    const int cx = i % W;
    const int t  = i / W;
    const int cy = t % H;
    const int cz = t / H;

    const unsigned g  = ((unsigned)cy * P1) ^ ((unsigned)cz * P2);
    const unsigned h0 = ((unsigned)cx ^ g) & T_MASK;
    const unsigned h1 = ((unsigned)(cx + 1) ^ g) & T_MASK;

    const float2 a = __ldg(&table[h0]);
    const float2 b = __ldg(&table[h1]);
    g_dense[p.off[l] + i] = make_float4(a.x, a.y, b.x, b.y);
}

// ------------------------------------------------------------------- main
__device__ __forceinline__ void lerp_accum(
    float2 v000, float2 v100, float2 v010, float2 v110,
    float2 v001, float2 v101, float2 v011, float2 v111,
    float dx, float dy, float dz, float2* acc)
{
    const float wx0 = 1.0f - dx, wx1 = dx;
    const float wy0 = 1.0f - dy, wy1 = dy;
    const float wz0 = 1.0f - dz, wz1 = dz;

    float a00x = v000.x * wx0 + v100.x * wx1;
    float a00y = v000.y * wx0 + v100.y * wx1;
    float a10x = v010.x * wx0 + v110.x * wx1;
    float a10y = v010.y * wx0 + v110.y * wx1;
    float a01x = v001.x * wx0 + v101.x * wx1;
    float a01y = v001.y * wx0 + v101.y * wx1;
    float a11x = v011.x * wx0 + v111.x * wx1;
    float a11y = v011.y * wx0 + v111.y * wx1;

    float b0x = a00x * wy0 + a10x * wy1;
    float b0y = a00y * wy0 + a10y * wy1;
    float b1x = a01x * wy0 + a11x * wy1;
    float b1y = a01y * wy0 + a11y * wy1;

    acc->x = b0x * wz0 + b1x * wz1;
    acc->y = b0y * wz0 + b1y * wz1;
}

__global__ __launch_bounds__(256) void hashgrid_kernel(
    const float2* __restrict__ table,
    float4* __restrict__ out,           // [N,8] float4
    Params p, int N)
{
    const int i = blockIdx.x * 256 + threadIdx.x;
    if (i >= N) return;

    const float4 xi = g_xs[i];
    const float px = xi.x, py = xi.y, pz = xi.z;
    const int   n  = __float_as_int(xi.w);

    float2 acc[N_LEVELS];

    // ---- dense levels 0..13: 4 spatially-local float4 loads ----
    #pragma unroll
    for (int l = 0; l < N_DENSE; ++l) {
        const float res = p.resf[l];
        const int r = (int)res;
        const int W = r, H = r + 1;

        const float sx = px * res;
        const float sy = py * res;
        const float sz = pz * res;

        int ix0 = (int)floorf(sx);
        int iy0 = (int)floorf(sy);
        int iz0 = (int)floorf(sz);
        // edge clamp: shifts cell down with d=1.0 (weight-0 corner swap,
        // identical result to reference)
        if (ix0 > W - 1) ix0 = W - 1;
        if (iy0 > H - 2) iy0 = H - 2;
        if (iz0 > H - 2) iz0 = H - 2;

        const float dx = sx - (float)ix0;
        const float dy = sy - (float)iy0;
        const float dz = sz - (float)iz0;

        const float4* __restrict__ G = g_dense + p.off[l];
        const int i00 = (iz0 * H + iy0) * W + ix0;
        const int i10 = i00 + W;
        const int i01 = i00 + W * H;
        const int i11 = i01 + W;

        const float4 q00 = __ldg(&G[i00]);
        const float4 q10 = __ldg(&G[i10]);
        const float4 q01 = __ldg(&G[i01]);
        const float4 q11 = __ldg(&G[i11]);

        lerp_accum(make_float2(q00.x, q00.y), make_float2(q00.z, q00.w),
                   make_float2(q10.x, q10.y), make_float2(q10.z, q10.w),
                   make_float2(q01.x, q01.y), make_float2(q01.z, q01.w),
                   make_float2(q11.x, q11.y), make_float2(q11.z, q11.w),
                   dx, dy, dz, &acc[l]);
    }

    // ---- hash levels 14..15: x-pair float4 merge + predicated odd load ----
    #pragma unroll
    for (int l = N_DENSE; l < N_LEVELS; ++l) {
        const float res = p.resf[l];
        const float sx = px * res;
        const float sy = py * res;
        const float sz = pz * res;

        const float fx = floorf(sx);
        const float fy = floorf(sy);
        const float fz = floorf(sz);

        const float dx = sx - fx;
        const float dy = sy - fy;
        const float dz = sz - fz;

        const unsigned x0u = (unsigned)(int)fx;
        const unsigned hy0 = (unsigned)(int)fy * P1;
        const unsigned hy1 = hy0 + P1;
        const unsigned hz0 = (unsigned)(int)fz * P2;
        const unsigned hz1 = hz0 + P2;

        const unsigned g00 = hy0 ^ hz0;
        const unsigned g10 = hy1 ^ hz0;
        const unsigned g01 = hy0 ^ hz1;
        const unsigned g11 = hy1 ^ hz1;

        const unsigned h000 = (x0u ^ g00) & T_MASK;
        const unsigned h010 = (x0u ^ g10) & T_MASK;
        const unsigned h001 = (x0u ^ g01) & T_MASK;
        const unsigned h011 = (x0u ^ g11) & T_MASK;

        const unsigned x1u  = x0u + 1u;
        const unsigned h100 = (x1u ^ g00) & T_MASK;
        const unsigned h110 = (x1u ^ g10) & T_MASK;
        const unsigned h101 = (x1u ^ g01) & T_MASK;
        const unsigned h111 = (x1u ^ g11) & T_MASK;

        const bool xeven = (x0u & 1u) == 0u;

        const float4 q00 = __ldg((const float4*)&table[h000 & ~1u]);
        const float4 q10 = __ldg((const float4*)&table[h010 & ~1u]);
        const float4 q01 = __ldg((const float4*)&table[h001 & ~1u]);
        const float4 q11 = __ldg((const float4*)&table[h011 & ~1u]);

        float2 e00, e10, e01, e11;
        if (!xeven) {
            e00 = __ldg(&table[h100]);
            e10 = __ldg(&table[h110]);
            e01 = __ldg(&table[h101]);
            e11 = __ldg(&table[h111]);
        }

        const float2 q00lo = make_float2(q00.x, q00.y), q00hi = make_float2(q00.z, q00.w);
        const float2 q10lo = make_float2(q10.x, q10.y), q10hi = make_float2(q10.z, q10.w);
        const float2 q01lo = make_float2(q01.x, q01.y), q01hi = make_float2(q01.z, q01.w);
        const float2 q11lo = make_float2(q11.x, q11.y), q11hi = make_float2(q11.z, q11.w);

        const bool p00 = (h000 & 1u), p10 = (h010 & 1u), p01 = (h001 & 1u), p11 = (h011 & 1u);

        const float2 v000 = p00 ? q00hi : q00lo;
        const float2 v010 = p10 ? q10hi : q10lo;
        const float2 v001 = p01 ? q01hi : q01lo;
        const float2 v011 = p11 ? q11hi : q11lo;

        const float2 v100 = xeven ? (p00 ? q00lo : q00hi) : e00;
        const float2 v110 = xeven ? (p10 ? q10lo : q10hi) : e10;
        const float2 v101 = xeven ? (p01 ? q01lo : q01hi) : e01;
        const float2 v111 = xeven ? (p11 ? q11lo : q11hi) : e11;

        lerp_accum(v000, v100, v010, v110, v001, v101, v011, v111,
                   dx, dy, dz, &acc[l]);
    }

    float4* row = out + (size_t)n * 8;
    #pragma unroll
    for (int j = 0; j < 8; ++j) {
        row[j] = make_float4(acc[2 * j].x, acc[2 * j].y,
                             acc[2 * j + 1].x, acc[2 * j + 1].y);
    }
}

// ----------------------------------------------------------------- launch
extern "C" void kernel_launch(void* const* d_in, const int* in_sizes, int n_in,
                              void* d_out, int out_size)
{
    const float*  x     = (const float*)d_in[0];
    const float2* table = (const float2*)d_in[1];
    float4*       out   = (float4*)d_out;

    const int N = in_sizes[0] / 3;

    Params p;
    int total_cells = 0;
    {
        const double growth = exp((log(128.0) - log(16.0)) / (double)(N_LEVELS - 1));
        int off = 0;
        p.cum[0] = 0;
        for (int l = 0; l < N_LEVELS; ++l) {
            const int r = (int)floor(16.0 * pow(growth, (double)l));
            p.resf[l] = (float)r;
            if (l < N_DENSE) {
                p.off[l] = off;
                off += r * (r + 1) * (r + 1);
                p.cum[l + 1] = off;
            }
        }
        total_cells = off;   // ~2.72M <= G_CAP
    }

    const int pb = (N + 255) / 256;

    zero_hist_kernel<<<(N_BUCKETS + 255) / 256, 256>>>();
    hist_kernel<<<pb, 256>>>(x, N);
    scan_kernel<<<1, 1024>>>();
    scatter_kernel<<<pb, 256>>>(x, N);
    build_dense_kernel<<<(total_cells + 255) / 256, 256>>>(table, p);
    hashgrid_kernel<<<pb, 256>>>(table, out, p, N);
}

// round 13
// speedup vs baseline: 1.0852x; 1.0852x over previous
#include <cuda_runtime.h>
#include <math.h>
#include <stdint.h>

// Multiresolution hash-grid encoding, spatially-sorted gather (v3).
//
// Pipeline (graph-capturable, scratch in __device__ globals):
//  K1 hist    : Morton bucket (res 32); atomicAdd gives rank; store packed
//               key = bucket | rank<<15 (one 4B store per point)
//  K2 scan    : exclusive scan of histogram -> bucket bases, then restores
//               g_hist to zero (self-cleaning: .bss starts zero, every call
//               consumes-and-zeros -> no separate memset kernel)
//  K3 scatter : pos = base[bucket] + rank (no atomics); streaming-store
//               sorted float4(x,y,z, idx-bits)
//  K4 main    : one thread per sorted point (warp = 32 spatially adjacent
//               points -> L1 merges same-line gathers). 16-level loop with
//               x-pair float4 hash merge; row buffered in registers and
//               streamed out as 8 float4 (__stcs, write-once data).

#define N_LEVELS 16
#define LOG2_T   19
#define T_MASK   ((1u << LOG2_T) - 1u)
#define P1       2654435761u
#define P2       805459861u

#define SORT_RES   32
#define N_BUCKETS  (SORT_RES * SORT_RES * SORT_RES)   // 32768 = 2^15
#define MAX_N      1100000

__device__ unsigned g_hist[N_BUCKETS];   // zero-init; scan restores zeros
__device__ unsigned g_base[N_BUCKETS];
__device__ unsigned g_key[MAX_N];        // bucket | rank<<15
__device__ float4   g_xs[MAX_N];         // sorted (x,y,z, idx-as-bits)

struct Params { float resf[N_LEVELS]; };

// ------------------------------------------------------------------ morton
__device__ __forceinline__ unsigned expand_bits(unsigned v) {
    v = (v * 0x00010001u) & 0xFF0000FFu;
    v = (v * 0x00000101u) & 0x0F00F00Fu;
    v = (v * 0x00000011u) & 0xC30C30C3u;
    v = (v * 0x00000005u) & 0x49249249u;
    return v;
}

__device__ __forceinline__ unsigned bucket_of(float px, float py, float pz) {
    int cx = (int)(px * (float)SORT_RES);
    int cy = (int)(py * (float)SORT_RES);
    int cz = (int)(pz * (float)SORT_RES);
    cx = min(max(cx, 0), SORT_RES - 1);
    cy = min(max(cy, 0), SORT_RES - 1);
    cz = min(max(cz, 0), SORT_RES - 1);
    return expand_bits((unsigned)cx)
         | (expand_bits((unsigned)cy) << 1)
         | (expand_bits((unsigned)cz) << 2);
}

// ---------------------------------------------------------------- kernels
__global__ __launch_bounds__(256) void hist_kernel(const float* __restrict__ x, int N) {
    int n = blockIdx.x * 256 + threadIdx.x;
    if (n >= N) return;
    unsigned b = bucket_of(x[n * 3 + 0], x[n * 3 + 1], x[n * 3 + 2]);
    unsigned r = atomicAdd(&g_hist[b], 1u);   // rank within bucket
    g_key[n] = b | (r << 15);                 // bucket: 15 bits, rank: 17 bits
}

__global__ __launch_bounds__(1024) void scan_kernel() {
    __shared__ unsigned partial[1024];
    const int t = threadIdx.x;
    unsigned local[32];
    unsigned s = 0;
    #pragma unroll
    for (int j = 0; j < 32; ++j) {
        local[j] = g_hist[t * 32 + j];
        g_hist[t * 32 + j] = 0u;        // restore zero-invariant for next call
        s += local[j];
    }
    partial[t] = s;
    __syncthreads();
    for (int d = 1; d < 1024; d <<= 1) {
        unsigned v = (t >= d) ? partial[t - d] : 0u;
        __syncthreads();
        partial[t] += v;
        __syncthreads();
    }
    unsigned run = (t > 0) ? partial[t - 1] : 0u;
    #pragma unroll
    for (int j = 0; j < 32; ++j) { g_base[t * 32 + j] = run; run += local[j]; }
}

__global__ __launch_bounds__(256) void scatter_kernel(const float* __restrict__ x, int N) {
    int n = blockIdx.x * 256 + threadIdx.x;
    if (n >= N) return;
    const unsigned k = g_key[n];
    const unsigned pos = g_base[k & (N_BUCKETS - 1)] + (k >> 15);   // no atomics
    const float4 v = make_float4(x[n * 3 + 0], x[n * 3 + 1], x[n * 3 + 2],
                                 __int_as_float(n));
    __stcs(&g_xs[pos], v);    // scattered, written once, read once -> evict-first
}

// ------------------------------------------------------------------- main
__global__ __launch_bounds__(256) void hashgrid_kernel(
    const float2* __restrict__ table,   // [T] float2
    float4* __restrict__ out,           // [N,16] float2 viewed as [N,8] float4
    Params p, int N)
{
    const int i = blockIdx.x * 256 + threadIdx.x;
    if (i >= N) return;

    const float4 xi = g_xs[i];          // coalesced
    const float px = xi.x, py = xi.y, pz = xi.z;
    const int   n  = __float_as_int(xi.w);

    float2 acc[N_LEVELS];

    #pragma unroll
    for (int l = 0; l < N_LEVELS; ++l) {
        const float res = p.resf[l];
        const float sx = px * res;
        const float sy = py * res;
        const float sz = pz * res;

        const float fx = floorf(sx);
        const float fy = floorf(sy);
        const float fz = floorf(sz);

        const float dx = sx - fx;
        const float dy = sy - fy;
        const float dz = sz - fz;

        const unsigned x0u = (unsigned)(int)fx;
        const unsigned hy0 = (unsigned)(int)fy * P1;
        const unsigned hy1 = hy0 + P1;
        const unsigned hz0 = (unsigned)(int)fz * P2;
        const unsigned hz1 = hz0 + P2;

        const unsigned g00 = hy0 ^ hz0;
        const unsigned g10 = hy1 ^ hz0;
        const unsigned g01 = hy0 ^ hz1;
        const unsigned g11 = hy1 ^ hz1;

        const unsigned h000 = (x0u ^ g00) & T_MASK;
        const unsigned h010 = (x0u ^ g10) & T_MASK;
        const unsigned h001 = (x0u ^ g01) & T_MASK;
        const unsigned h011 = (x0u ^ g11) & T_MASK;

        const unsigned x1u  = x0u + 1u;
        const unsigned h100 = (x1u ^ g00) & T_MASK;
        const unsigned h110 = (x1u ^ g10) & T_MASK;
        const unsigned h101 = (x1u ^ g01) & T_MASK;
        const unsigned h111 = (x1u ^ g11) & T_MASK;

        const bool xeven = (x0u & 1u) == 0u;

        // 4 float4 loads always cover the x0 corners (and x1 when x0 even)
        const float4 q00 = __ldg((const float4*)&table[h000 & ~1u]);
        const float4 q10 = __ldg((const float4*)&table[h010 & ~1u]);
        const float4 q01 = __ldg((const float4*)&table[h001 & ~1u]);
        const float4 q11 = __ldg((const float4*)&table[h011 & ~1u]);

        float2 e00, e10, e01, e11;
        if (!xeven) {
            e00 = __ldg(&table[h100]);
            e10 = __ldg(&table[h110]);
            e01 = __ldg(&table[h101]);
            e11 = __ldg(&table[h111]);
        }

        const float2 q00lo = make_float2(q00.x, q00.y), q00hi = make_float2(q00.z, q00.w);
        const float2 q10lo = make_float2(q10.x, q10.y), q10hi = make_float2(q10.z, q10.w);
        const float2 q01lo = make_float2(q01.x, q01.y), q01hi = make_float2(q01.z, q01.w);
        const float2 q11lo = make_float2(q11.x, q11.y), q11hi = make_float2(q11.z, q11.w);

        const bool p00 = (h000 & 1u), p10 = (h010 & 1u), p01 = (h001 & 1u), p11 = (h011 & 1u);

        const float2 v000 = p00 ? q00hi : q00lo;
        const float2 v010 = p10 ? q10hi : q10lo;
        const float2 v001 = p01 ? q01hi : q01lo;
        const float2 v011 = p11 ? q11hi : q11lo;

        const float2 v100 = xeven ? (p00 ? q00lo : q00hi) : e00;
        const float2 v110 = xeven ? (p10 ? q10lo : q10hi) : e10;
        const float2 v101 = xeven ? (p01 ? q01lo : q01hi) : e01;
        const float2 v111 = xeven ? (p11 ? q11lo : q11hi) : e11;

        const float wx0 = 1.0f - dx, wx1 = dx;
        const float wy0 = 1.0f - dy, wy1 = dy;
        const float wz0 = 1.0f - dz, wz1 = dz;

        float a00x = v000.x * wx0 + v100.x * wx1;
        float a00y = v000.y * wx0 + v100.y * wx1;
        float a10x = v010.x * wx0 + v110.x * wx1;
        float a10y = v010.y * wx0 + v110.y * wx1;
        float a01x = v001.x * wx0 + v101.x * wx1;
        float a01y = v001.y * wx0 + v101.y * wx1;
        float a11x = v011.x * wx0 + v111.x * wx1;
        float a11y = v011.y * wx0 + v111.y * wx1;

        float b0x = a00x * wy0 + a10x * wy1;
        float b0y = a00y * wy0 + a10y * wy1;
        float b1x = a01x * wy0 + a11x * wy1;
        float b1y = a01y * wy0 + a11y * wy1;

        acc[l].x = b0x * wz0 + b1x * wz1;
        acc[l].y = b0y * wz0 + b1y * wz1;
    }

    // Stream full 128B row as 8 float4 (write-once -> evict-first).
    float4* row = out + (size_t)n * 8;
    #pragma unroll
    for (int j = 0; j < 8; ++j) {
        __stcs(&row[j], make_float4(acc[2 * j].x, acc[2 * j].y,
                                    acc[2 * j + 1].x, acc[2 * j + 1].y));
    }
}

// ----------------------------------------------------------------- launch
extern "C" void kernel_launch(void* const* d_in, const int* in_sizes, int n_in,
                              void* d_out, int out_size)
{
    const float*  x     = (const float*)d_in[0];
    const float2* table = (const float2*)d_in[1];
    float4*       out   = (float4*)d_out;

    const int N = in_sizes[0] / 3;

    Params p;
    {
        const double growth = exp((log(128.0) - log(16.0)) / (double)(N_LEVELS - 1));
        for (int l = 0; l < N_LEVELS; ++l)
            p.resf[l] = (float)floor(16.0 * pow(growth, (double)l));
    }

    const int pb = (N + 255) / 256;

    hist_kernel<<<pb, 256>>>(x, N);
    scan_kernel<<<1, 1024>>>();
    scatter_kernel<<<pb, 256>>>(x, N);
    hashgrid_kernel<<<pb, 256>>>(table, out, p, N);
}

// round 14
// speedup vs baseline: 1.2495x; 1.1514x over previous
#include <cuda_runtime.h>
#include <math.h>
#include <stdint.h>

// Multiresolution hash-grid encoding, spatially-sorted gather (v4).
//
//  K1 hist    : Morton bucket (res 32); atomicAdd rank; packed key store
//  K2 scan    : exclusive scan -> bucket bases; restores g_hist zeros
//  K3 scatter : pos = base+rank (no atomics); plain float4 store (the
//               __stcs here in v3 regressed the pipeline -- reverted)
//  K4 main    : one thread per sorted point. 16-level loop, x-pair float4
//               hash merge. NEW: results staged in padded smem and stored
//               via a warp transpose -- each STG.128 has 8-lane groups
//               writing whole 128B rows contiguously: 4 wavefronts/instr
//               instead of 32 (8x fewer store wavefronts).

#define N_LEVELS 16
#define LOG2_T   19
#define T_MASK   ((1u << LOG2_T) - 1u)
#define P1       2654435761u
#define P2       805459861u

#define SORT_RES   32
#define N_BUCKETS  (SORT_RES * SORT_RES * SORT_RES)   // 2^15
#define MAX_N      1100000

#define TPB       256
#define ROW_PAD   9          // float4 units per row in smem (8 data + 1 pad)

__device__ unsigned g_hist[N_BUCKETS];   // zero-init; scan restores zeros
__device__ unsigned g_base[N_BUCKETS];
__device__ unsigned g_key[MAX_N];        // bucket | rank<<15
__device__ float4   g_xs[MAX_N];         // sorted (x,y,z, idx-as-bits)

struct Params { float resf[N_LEVELS]; };

// ------------------------------------------------------------------ morton
__device__ __forceinline__ unsigned expand_bits(unsigned v) {
    v = (v * 0x00010001u) & 0xFF0000FFu;
    v = (v * 0x00000101u) & 0x0F00F00Fu;
    v = (v * 0x00000011u) & 0xC30C30C3u;
    v = (v * 0x00000005u) & 0x49249249u;
    return v;
}

__device__ __forceinline__ unsigned bucket_of(float px, float py, float pz) {
    int cx = (int)(px * (float)SORT_RES);
    int cy = (int)(py * (float)SORT_RES);
    int cz = (int)(pz * (float)SORT_RES);
    cx = min(max(cx, 0), SORT_RES - 1);
    cy = min(max(cy, 0), SORT_RES - 1);
    cz = min(max(cz, 0), SORT_RES - 1);
    return expand_bits((unsigned)cx)
         | (expand_bits((unsigned)cy) << 1)
         | (expand_bits((unsigned)cz) << 2);
}

// ---------------------------------------------------------------- kernels
__global__ __launch_bounds__(TPB) void hist_kernel(const float* __restrict__ x, int N) {
    int n = blockIdx.x * TPB + threadIdx.x;
    if (n >= N) return;
    unsigned b = bucket_of(x[n * 3 + 0], x[n * 3 + 1], x[n * 3 + 2]);
    unsigned r = atomicAdd(&g_hist[b], 1u);
    g_key[n] = b | (r << 15);
}

__global__ __launch_bounds__(1024) void scan_kernel() {
    __shared__ unsigned partial[1024];
    const int t = threadIdx.x;
    unsigned local[32];
    unsigned s = 0;
    #pragma unroll
    for (int j = 0; j < 32; ++j) {
        local[j] = g_hist[t * 32 + j];
        g_hist[t * 32 + j] = 0u;        // restore zero-invariant
        s += local[j];
    }
    partial[t] = s;
    __syncthreads();
    for (int d = 1; d < 1024; d <<= 1) {
        unsigned v = (t >= d) ? partial[t - d] : 0u;
        __syncthreads();
        partial[t] += v;
        __syncthreads();
    }
    unsigned run = (t > 0) ? partial[t - 1] : 0u;
    #pragma unroll
    for (int j = 0; j < 32; ++j) { g_base[t * 32 + j] = run; run += local[j]; }
}

__global__ __launch_bounds__(TPB) void scatter_kernel(const float* __restrict__ x, int N) {
    int n = blockIdx.x * TPB + threadIdx.x;
    if (n >= N) return;
    const unsigned k = g_key[n];
    const unsigned pos = g_base[k & (N_BUCKETS - 1)] + (k >> 15);
    g_xs[pos] = make_float4(x[n * 3 + 0], x[n * 3 + 1], x[n * 3 + 2],
                            __int_as_float(n));
}

// ------------------------------------------------------------------- main
__global__ __launch_bounds__(TPB) void hashgrid_kernel(
    const float2* __restrict__ table,   // [T] float2
    float4* __restrict__ out,           // [N,8] float4 rows
    Params p, int N)
{
    __shared__ float4 s_row[TPB * ROW_PAD];   // 36 KB
    __shared__ int    s_n[TPB];

    const int tid  = threadIdx.x;
    const int lane = tid & 31;
    const int i = blockIdx.x * TPB + tid;
    const bool valid = (i < N);

    int n = -1;
    if (valid) {
        const float4 xi = g_xs[i];          // coalesced
        const float px = xi.x, py = xi.y, pz = xi.z;
        n = __float_as_int(xi.w);

        #pragma unroll
        for (int l = 0; l < N_LEVELS; l += 2) {
            float2 pr[2];
            #pragma unroll
            for (int s = 0; s < 2; ++s) {
                const float res = p.resf[l + s];
                const float sx = px * res;
                const float sy = py * res;
                const float sz = pz * res;

                const float fx = floorf(sx);
                const float fy = floorf(sy);
                const float fz = floorf(sz);

                const float dx = sx - fx;
                const float dy = sy - fy;
                const float dz = sz - fz;

                const unsigned x0u = (unsigned)(int)fx;
                const unsigned hy0 = (unsigned)(int)fy * P1;
                const unsigned hy1 = hy0 + P1;
                const unsigned hz0 = (unsigned)(int)fz * P2;
                const unsigned hz1 = hz0 + P2;

                const unsigned g00 = hy0 ^ hz0;
                const unsigned g10 = hy1 ^ hz0;
                const unsigned g01 = hy0 ^ hz1;
                const unsigned g11 = hy1 ^ hz1;

                const unsigned h000 = (x0u ^ g00) & T_MASK;
                const unsigned h010 = (x0u ^ g10) & T_MASK;
                const unsigned h001 = (x0u ^ g01) & T_MASK;
                const unsigned h011 = (x0u ^ g11) & T_MASK;

                const unsigned x1u  = x0u + 1u;
                const unsigned h100 = (x1u ^ g00) & T_MASK;
                const unsigned h110 = (x1u ^ g10) & T_MASK;
                const unsigned h101 = (x1u ^ g01) & T_MASK;
                const unsigned h111 = (x1u ^ g11) & T_MASK;

                const bool xeven = (x0u & 1u) == 0u;

                const float4 q00 = __ldg((const float4*)&table[h000 & ~1u]);
                const float4 q10 = __ldg((const float4*)&table[h010 & ~1u]);
                const float4 q01 = __ldg((const float4*)&table[h001 & ~1u]);
                const float4 q11 = __ldg((const float4*)&table[h011 & ~1u]);

                float2 e00, e10, e01, e11;
                if (!xeven) {
                    e00 = __ldg(&table[h100]);
                    e10 = __ldg(&table[h110]);
                    e01 = __ldg(&table[h101]);
                    e11 = __ldg(&table[h111]);
                }

                const float2 q00lo = make_float2(q00.x, q00.y), q00hi = make_float2(q00.z, q00.w);
                const float2 q10lo = make_float2(q10.x, q10.y), q10hi = make_float2(q10.z, q10.w);
                const float2 q01lo = make_float2(q01.x, q01.y), q01hi = make_float2(q01.z, q01.w);
                const float2 q11lo = make_float2(q11.x, q11.y), q11hi = make_float2(q11.z, q11.w);

                const bool p00 = (h000 & 1u), p10 = (h010 & 1u),
                           p01 = (h001 & 1u), p11 = (h011 & 1u);

                const float2 v000 = p00 ? q00hi : q00lo;
                const float2 v010 = p10 ? q10hi : q10lo;
                const float2 v001 = p01 ? q01hi : q01lo;
                const float2 v011 = p11 ? q11hi : q11lo;

                const float2 v100 = xeven ? (p00 ? q00lo : q00hi) : e00;
                const float2 v110 = xeven ? (p10 ? q10lo : q10hi) : e10;
                const float2 v101 = xeven ? (p01 ? q01lo : q01hi) : e01;
                const float2 v111 = xeven ? (p11 ? q11lo : q11hi) : e11;

                const float wx0 = 1.0f - dx, wx1 = dx;
                const float wy0 = 1.0f - dy, wy1 = dy;
                const float wz0 = 1.0f - dz, wz1 = dz;

                float a00x = v000.x * wx0 + v100.x * wx1;
                float a00y = v000.y * wx0 + v100.y * wx1;
                float a10x = v010.x * wx0 + v110.x * wx1;
                float a10y = v010.y * wx0 + v110.y * wx1;
                float a01x = v001.x * wx0 + v101.x * wx1;
                float a01y = v001.y * wx0 + v101.y * wx1;
                float a11x = v011.x * wx0 + v111.x * wx1;
                float a11y = v011.y * wx0 + v111.y * wx1;

                float b0x = a00x * wy0 + a10x * wy1;
                float b0y = a00y * wy0 + a10y * wy1;
                float b1x = a01x * wy0 + a11x * wy1;
                float b1y = a01y * wy0 + a11y * wy1;

                pr[s].x = b0x * wz0 + b1x * wz1;
                pr[s].y = b0y * wz0 + b1y * wz1;
            }
            s_row[tid * ROW_PAD + (l >> 1)] =
                make_float4(pr[0].x, pr[0].y, pr[1].x, pr[1].y);
        }
    }
    s_n[tid] = n;
    __syncwarp();

    // Warp transpose store: per instruction, 4 groups of 8 lanes each write
    // one full 128B output row contiguously -> 4 lines = 4 wavefronts.
    const int wbase = tid & ~31;
    const int chunk = lane & 7;
    #pragma unroll
    for (int iter = 0; iter < 8; ++iter) {
        const int row = wbase + iter * 4 + (lane >> 3);
        const int nn = s_n[row];
        if (nn >= 0) {
            __stcs(&out[(size_t)nn * 8 + chunk], s_row[row * ROW_PAD + chunk]);
        }
    }
}

// ----------------------------------------------------------------- launch
extern "C" void kernel_launch(void* const* d_in, const int* in_sizes, int n_in,
                              void* d_out, int out_size)
{
    const float*  x     = (const float*)d_in[0];
    const float2* table = (const float2*)d_in[1];
    float4*       out   = (float4*)d_out;

    const int N = in_sizes[0] / 3;

    Params p;
    {
        const double growth = exp((log(128.0) - log(16.0)) / (double)(N_LEVELS - 1));
        for (int l = 0; l < N_LEVELS; ++l)
            p.resf[l] = (float)floor(16.0 * pow(growth, (double)l));
    }

    const int pb = (N + TPB - 1) / TPB;

    hist_kernel<<<pb, TPB>>>(x, N);
    scan_kernel<<<1, 1024>>>();
    scatter_kernel<<<pb, TPB>>>(x, N);
    hashgrid_kernel<<<pb, TPB>>>(table, out, p, N);
}